// round 1
// baseline (speedup 1.0000x reference)
#include <cuda_runtime.h>
#include <cuda_bf16.h>
#include <math.h>

#define BB 16
#define TT 4096
#define DD 512
#define CCH 10
#define FWD 100
#define KW 201          // 2*FW+1
#define NBLK 4          // N split: 4 tiles of 128 columns

// ---------------- device scratch (static, allowed) ----------------
__device__ __nv_bfloat16 g_Whi[DD * DD];
__device__ __nv_bfloat16 g_Wlo[DD * DD];
__device__ float g_dec[BB * DD];                 // dec projection + b_enc
__device__ float g_conv[BB * TT * CCH];          // conv features [b][t][c]
__device__ float g_epart[NBLK * BB * TT];        // partial logits per N-block
__device__ float g_ctxpart[8 * BB * DD];         // context partials per T-chunk

// ---------------- helpers ----------------
__device__ __forceinline__ unsigned pack_bf2(float x, float y) {
    __nv_bfloat162 h = __floats2bfloat162_rn(x, y);   // .x = low half
    return *reinterpret_cast<unsigned*>(&h);
}

__device__ __forceinline__ void mma_bf16(float* d, const unsigned* a,
                                         unsigned b0, unsigned b1) {
    asm volatile(
        "mma.sync.aligned.m16n8k16.row.col.f32.bf16.bf16.f32 "
        "{%0,%1,%2,%3}, {%4,%5,%6,%7}, {%8,%9}, {%0,%1,%2,%3};\n"
        : "+f"(d[0]), "+f"(d[1]), "+f"(d[2]), "+f"(d[3])
        : "r"(a[0]), "r"(a[1]), "r"(a[2]), "r"(a[3]), "r"(b0), "r"(b1));
}

// ---------------- kernel 1: split W_enc into bf16 hi/lo ----------------
__global__ void k_split(const float* __restrict__ W) {
    int i = blockIdx.x * blockDim.x + threadIdx.x;   // 262144 total
    float w = W[i];
    __nv_bfloat16 hi = __float2bfloat16(w);
    float r = w - __bfloat162float(hi);
    g_Whi[i] = hi;
    g_Wlo[i] = __float2bfloat16(r);
}

// ---------------- kernel 2: dec projection + b_enc ----------------
__global__ void k_dec(const float* __restrict__ query,
                      const float* __restrict__ Wdec,
                      const float* __restrict__ b_enc) {
    __shared__ float q[DD];
    int b = blockIdx.x;
    int e = threadIdx.x;
    q[e] = query[b * DD + e];
    __syncthreads();
    float acc = b_enc[e];
    const float* wr = Wdec + e * DD;
#pragma unroll 8
    for (int d = 0; d < DD; ++d) acc += q[d] * wr[d];
    g_dec[b * DD + e] = acc;
}

// ---------------- kernel 3: location conv (att_prev -> [b][t][10]) ------
__global__ void k_conv(const float* __restrict__ att_prev,
                       const float* __restrict__ Wconv) {
    __shared__ float win[128 + 2 * FWD];   // 328
    __shared__ float wc[CCH * KW];         // 2010
    int t0 = blockIdx.x * 128;
    int b = blockIdx.y;
    int tid = threadIdx.x;                 // 128
    for (int i = tid; i < 128 + 2 * FWD; i += 128) {
        int gidx = t0 - FWD + i;
        win[i] = (gidx >= 0 && gidx < TT) ? att_prev[b * TT + gidx] : 0.f;
    }
    for (int i = tid; i < CCH * KW; i += 128) wc[i] = Wconv[i];
    __syncthreads();
    float acc[CCH];
#pragma unroll
    for (int c = 0; c < CCH; ++c) acc[c] = 0.f;
    for (int h = 0; h < KW; ++h) {
        float x = win[tid + h];
#pragma unroll
        for (int c = 0; c < CCH; ++c) acc[c] += x * wc[c * KW + h];
    }
    float* o = &g_conv[(size_t)(b * TT + t0 + tid) * CCH];
#pragma unroll
    for (int c = 0; c < CCH; ++c) o[c] = acc[c];
}

// ---------------- kernel 4: fused split-bf16 GEMM + epilogue -> logits --
// block tile: 128(t) x 128(e), K=512, split-K none, 256 threads (8 warps 4x2)
#define KC 32
struct SMain {
    unsigned Ahi[2][128][12];
    unsigned Alo[2][128][12];
    unsigned Bhi[2][128][12];
    unsigned Blo[2][128][12];
};                                      // 49152 bytes
struct SEpi {
    float conv[128][10];
    float watt[128][10];
    float dec[128];
    float wg[128];
    float red[128][2];
};
union SU { SMain m; SEpi e; };

__global__ void __launch_bounds__(256)
k_gemm(const float* __restrict__ value,
       const float* __restrict__ Watt,
       const float* __restrict__ wg) {
    __shared__ SU su;
    int tid = threadIdx.x;
    int b = blockIdx.z;
    int t0 = blockIdx.x * 128;
    int e0 = blockIdx.y * 128;
    int lane = tid & 31, warp = tid >> 5;
    int wm = warp & 3, wn = warp >> 2;         // 4 x 2 warps
    int g = lane >> 2, c = lane & 3;

    float acc[2][8][4];
#pragma unroll
    for (int mt = 0; mt < 2; ++mt)
#pragma unroll
        for (int nt = 0; nt < 8; ++nt)
#pragma unroll
            for (int q = 0; q < 4; ++q) acc[mt][nt][q] = 0.f;

    const float* Abase = value + ((size_t)b * TT + t0) * DD;
    int arow = tid >> 1, ahalf = tid & 1;

    for (int k0 = 0; k0 < DD; k0 += KC) {
        // stage A (fp32 -> bf16 hi/lo split on the fly)
#pragma unroll
        for (int i = 0; i < 4; ++i) {
            int jj = ahalf * 4 + i;                        // float4 idx 0..7
            float4 v = *(const float4*)(Abase + (size_t)arow * DD + k0 + jj * 4);
            int ks = jj >> 2;
            int w0 = (jj & 3) * 2;
            __nv_bfloat16 h0 = __float2bfloat16(v.x);
            __nv_bfloat16 h1 = __float2bfloat16(v.y);
            __nv_bfloat16 h2 = __float2bfloat16(v.z);
            __nv_bfloat16 h3 = __float2bfloat16(v.w);
            float r0 = v.x - __bfloat162float(h0);
            float r1 = v.y - __bfloat162float(h1);
            float r2 = v.z - __bfloat162float(h2);
            float r3 = v.w - __bfloat162float(h3);
            __nv_bfloat162 p01; p01.x = h0; p01.y = h1;
            __nv_bfloat162 p23; p23.x = h2; p23.y = h3;
            su.m.Ahi[ks][arow][w0]     = *reinterpret_cast<unsigned*>(&p01);
            su.m.Ahi[ks][arow][w0 + 1] = *reinterpret_cast<unsigned*>(&p23);
            su.m.Alo[ks][arow][w0]     = pack_bf2(r0, r1);
            su.m.Alo[ks][arow][w0 + 1] = pack_bf2(r2, r3);
        }
        // stage B (already bf16 hi/lo in global)
#pragma unroll
        for (int p = 0; p < 2; ++p) {
            int i = tid + p * 256;                         // 0..511
            int row = i >> 2, u = i & 3;
            int ks = u >> 1, w0 = (u & 1) * 4;
            uint4 hv = *(const uint4*)(g_Whi + (size_t)(e0 + row) * DD + k0 + u * 8);
            su.m.Bhi[ks][row][w0 + 0] = hv.x;
            su.m.Bhi[ks][row][w0 + 1] = hv.y;
            su.m.Bhi[ks][row][w0 + 2] = hv.z;
            su.m.Bhi[ks][row][w0 + 3] = hv.w;
            uint4 lv = *(const uint4*)(g_Wlo + (size_t)(e0 + row) * DD + k0 + u * 8);
            su.m.Blo[ks][row][w0 + 0] = lv.x;
            su.m.Blo[ks][row][w0 + 1] = lv.y;
            su.m.Blo[ks][row][w0 + 2] = lv.z;
            su.m.Blo[ks][row][w0 + 3] = lv.w;
        }
        __syncthreads();
#pragma unroll
        for (int ks = 0; ks < 2; ++ks) {
            unsigned ahi[2][4], alo[2][4];
#pragma unroll
            for (int mt = 0; mt < 2; ++mt) {
                int rb = wm * 32 + mt * 16;
                ahi[mt][0] = su.m.Ahi[ks][rb + g][c];
                ahi[mt][1] = su.m.Ahi[ks][rb + 8 + g][c];
                ahi[mt][2] = su.m.Ahi[ks][rb + g][c + 4];
                ahi[mt][3] = su.m.Ahi[ks][rb + 8 + g][c + 4];
                alo[mt][0] = su.m.Alo[ks][rb + g][c];
                alo[mt][1] = su.m.Alo[ks][rb + 8 + g][c];
                alo[mt][2] = su.m.Alo[ks][rb + g][c + 4];
                alo[mt][3] = su.m.Alo[ks][rb + 8 + g][c + 4];
            }
#pragma unroll
            for (int nt = 0; nt < 8; ++nt) {
                int nb = wn * 64 + nt * 8;
                unsigned bh0 = su.m.Bhi[ks][nb + g][c];
                unsigned bh1 = su.m.Bhi[ks][nb + g][c + 4];
                unsigned bl0 = su.m.Blo[ks][nb + g][c];
                unsigned bl1 = su.m.Blo[ks][nb + g][c + 4];
#pragma unroll
                for (int mt = 0; mt < 2; ++mt) {
                    mma_bf16(acc[mt][nt], ahi[mt], bh0, bh1);
                    mma_bf16(acc[mt][nt], ahi[mt], bl0, bl1);
                    mma_bf16(acc[mt][nt], alo[mt], bh0, bh1);
                }
            }
        }
        __syncthreads();
    }

    // ---- epilogue: + dec + conv@Watt, tanh, dot w_g, row-reduce ----
    for (int i = tid; i < 1280; i += 256) {
        int row = i / 10, cc = i - row * 10;
        su.e.conv[row][cc] = g_conv[(size_t)(b * TT + t0 + row) * CCH + cc];
        su.e.watt[row][cc] = Watt[(e0 + row) * CCH + cc];
    }
    if (tid < 128) {
        su.e.dec[tid] = g_dec[b * DD + e0 + tid];
        su.e.wg[tid] = wg[e0 + tid];
    }
    __syncthreads();

    float rowsum[2][2];
#pragma unroll
    for (int mt = 0; mt < 2; ++mt)
#pragma unroll
        for (int rr = 0; rr < 2; ++rr) {
            int rowl = wm * 32 + mt * 16 + rr * 8 + g;
            float s = 0.f;
#pragma unroll
            for (int nt = 0; nt < 8; ++nt)
#pragma unroll
                for (int q = 0; q < 2; ++q) {
                    int el = wn * 64 + nt * 8 + 2 * c + q;
                    float v = acc[mt][nt][rr * 2 + q] + su.e.dec[el];
#pragma unroll
                    for (int cc = 0; cc < CCH; ++cc)
                        v += su.e.conv[rowl][cc] * su.e.watt[el][cc];
                    s += su.e.wg[el] * tanhf(v);
                }
            rowsum[mt][rr] = s;
        }
    // reduce over the 4 lanes (c) sharing a row
#pragma unroll
    for (int mt = 0; mt < 2; ++mt)
#pragma unroll
        for (int rr = 0; rr < 2; ++rr) {
            float v = rowsum[mt][rr];
            v += __shfl_xor_sync(0xffffffffu, v, 1);
            v += __shfl_xor_sync(0xffffffffu, v, 2);
            rowsum[mt][rr] = v;
        }
    if (c == 0) {
#pragma unroll
        for (int mt = 0; mt < 2; ++mt)
#pragma unroll
            for (int rr = 0; rr < 2; ++rr)
                su.e.red[wm * 32 + mt * 16 + rr * 8 + g][wn] = rowsum[mt][rr];
    }
    __syncthreads();
    if (tid < 128) {
        float val = su.e.red[tid][0] + su.e.red[tid][1];
        g_epart[((size_t)blockIdx.y * BB + b) * TT + t0 + tid] = val;
    }
}

// ---------------- kernel 5: masked sharpened softmax ----------------
__global__ void k_softmax(const int* __restrict__ lens,
                          float* __restrict__ out_att) {
    int b = blockIdx.x;
    int tid = threadIdx.x;            // 256
    int len = lens[b];
    __shared__ float sred[256];
    float ev[16];
    float lmax = -INFINITY;
#pragma unroll
    for (int i = 0; i < 16; ++i) {
        int t = tid + i * 256;
        float e = g_epart[(0 * BB + b) * TT + t] +
                  g_epart[(1 * BB + b) * TT + t] +
                  g_epart[(2 * BB + b) * TT + t] +
                  g_epart[(3 * BB + b) * TT + t];
        e *= 2.0f;                    // sharpening
        ev[i] = (t < len) ? e : -INFINITY;
        lmax = fmaxf(lmax, ev[i]);
    }
    sred[tid] = lmax;
    __syncthreads();
    for (int s = 128; s > 0; s >>= 1) {
        if (tid < s) sred[tid] = fmaxf(sred[tid], sred[tid + s]);
        __syncthreads();
    }
    float m = sred[0];
    __syncthreads();
    float lsum = 0.f;
#pragma unroll
    for (int i = 0; i < 16; ++i) {
        float p = expf(ev[i] - m);    // exp(-inf)=0 for masked
        ev[i] = p;
        lsum += p;
    }
    sred[tid] = lsum;
    __syncthreads();
    for (int s = 128; s > 0; s >>= 1) {
        if (tid < s) sred[tid] += sred[tid + s];
        __syncthreads();
    }
    float inv = 1.f / sred[0];
#pragma unroll
    for (int i = 0; i < 16; ++i)
        out_att[b * TT + tid + i * 256] = ev[i] * inv;
}

// ---------------- kernel 6/7: context = value^T @ weights ----------------
__global__ void k_ctx_part(const float* __restrict__ value,
                           const float* __restrict__ att) {
    int dch = blockIdx.x, tch = blockIdx.y, b = blockIdx.z;
    int dl = threadIdx.x & 127;
    int tl = threadIdx.x >> 7;        // 0/1
    int d = dch * 128 + dl;
    const float* vb = value + (size_t)b * TT * DD;
    const float* ab = att + b * TT;
    float acc = 0.f;
    int tbase = tch * 512;
    for (int t = tbase + tl; t < tbase + 512; t += 2)
        acc += vb[(size_t)t * DD + d] * ab[t];
    __shared__ float s[256];
    s[threadIdx.x] = acc;
    __syncthreads();
    if (tl == 0)
        g_ctxpart[((size_t)tch * BB + b) * DD + d] = s[dl] + s[dl + 128];
}

__global__ void k_ctx_final(float* __restrict__ out) {
    int idx = blockIdx.x * 256 + threadIdx.x;    // < BB*DD
    float v = 0.f;
#pragma unroll
    for (int p = 0; p < 8; ++p) v += g_ctxpart[p * BB * DD + idx];
    out[idx] = v;
}

// ---------------- launch ----------------
extern "C" void kernel_launch(void* const* d_in, const int* in_sizes, int n_in,
                              void* d_out, int out_size) {
    const float* value    = (const float*)d_in[0];
    const float* query    = (const float*)d_in[1];
    const int*   lens     = (const int*)d_in[2];
    const float* att_prev = (const float*)d_in[3];
    const float* W_enc    = (const float*)d_in[4];
    const float* b_enc    = (const float*)d_in[5];
    const float* W_dec    = (const float*)d_in[6];
    const float* W_att    = (const float*)d_in[7];
    const float* W_conv   = (const float*)d_in[8];
    const float* w_g      = (const float*)d_in[9];
    // d_in[10] = b_g: uniform logit shift, cancels in softmax.

    float* out = (float*)d_out;
    float* out_att = out + BB * DD;

    k_split<<<512, 512>>>(W_enc);
    k_dec<<<BB, DD>>>(query, W_dec, b_enc);
    k_conv<<<dim3(TT / 128, BB), 128>>>(att_prev, W_conv);
    k_gemm<<<dim3(TT / 128, NBLK, BB), 256>>>(value, W_att, w_g);
    k_softmax<<<BB, 256>>>(lens, out_att);
    k_ctx_part<<<dim3(4, 8, BB), 256>>>(value, out_att);
    k_ctx_final<<<BB * DD / 256, 256>>>(out);
}

// round 2
// speedup vs baseline: 1.0301x; 1.0301x over previous
#include <cuda_runtime.h>
#include <cuda_bf16.h>
#include <math.h>

#define BB 16
#define TT 4096
#define DD 512
#define CCH 10
#define FWD 100
#define KW 201          // 2*FW+1
#define NBLK 4          // N split: 4 tiles of 128 columns

// ---------------- device scratch (static, allowed) ----------------
__device__ __align__(16) __nv_bfloat16 g_Whi[DD * DD];
__device__ __align__(16) __nv_bfloat16 g_Wlo[DD * DD];
__device__ __align__(16) __nv_bfloat16 g_Vhi[(size_t)BB * TT * DD];
__device__ __align__(16) __nv_bfloat16 g_Vlo[(size_t)BB * TT * DD];
__device__ float g_dec[BB * DD];                 // dec projection + b_enc
__device__ float g_conv[BB * TT * CCH];          // conv features [b][t][c]
__device__ float g_epart[NBLK * BB * TT];        // partial logits per N-block
__device__ float g_ctxpart[8 * BB * DD];         // context partials per T-chunk

// ---------------- helpers ----------------
__device__ __forceinline__ unsigned pack_bf2(float x, float y) {
    __nv_bfloat162 h = __floats2bfloat162_rn(x, y);   // .x = low half
    return *reinterpret_cast<unsigned*>(&h);
}

__device__ __forceinline__ void mma_bf16(float* d, const unsigned* a,
                                         unsigned b0, unsigned b1) {
    asm volatile(
        "mma.sync.aligned.m16n8k16.row.col.f32.bf16.bf16.f32 "
        "{%0,%1,%2,%3}, {%4,%5,%6,%7}, {%8,%9}, {%0,%1,%2,%3};\n"
        : "+f"(d[0]), "+f"(d[1]), "+f"(d[2]), "+f"(d[3])
        : "r"(a[0]), "r"(a[1]), "r"(a[2]), "r"(a[3]), "r"(b0), "r"(b1));
}

__device__ __forceinline__ void ldsm4(unsigned* r, unsigned addr) {
    asm volatile("ldmatrix.sync.aligned.m8n8.x4.shared.b16 {%0,%1,%2,%3}, [%4];\n"
                 : "=r"(r[0]), "=r"(r[1]), "=r"(r[2]), "=r"(r[3]) : "r"(addr));
}

#define CP_ASYNC16(sm, gm) \
    asm volatile("cp.async.cg.shared.global [%0], [%1], 16;\n" :: "r"(sm), "l"(gm))
#define CP_COMMIT() asm volatile("cp.async.commit_group;\n")
#define CP_WAIT(n)  asm volatile("cp.async.wait_group %0;\n" :: "n"(n))

// ---------------- kernel 1: split W_enc into bf16 hi/lo ----------------
__global__ void k_split(const float* __restrict__ W) {
    int i = blockIdx.x * blockDim.x + threadIdx.x;   // 262144 total
    float w = W[i];
    __nv_bfloat16 hi = __float2bfloat16(w);
    float r = w - __bfloat162float(hi);
    g_Whi[i] = hi;
    g_Wlo[i] = __float2bfloat16(r);
}

// ---------------- kernel 1b: split value into bf16 hi/lo ----------------
__global__ void __launch_bounds__(256) k_vsplit(const float* __restrict__ v) {
    size_t i = ((size_t)blockIdx.x * 256 + threadIdx.x) * 4;
    float4 x = *(const float4*)(v + i);
    __nv_bfloat16 h0 = __float2bfloat16(x.x);
    __nv_bfloat16 h1 = __float2bfloat16(x.y);
    __nv_bfloat16 h2 = __float2bfloat16(x.z);
    __nv_bfloat16 h3 = __float2bfloat16(x.w);
    float r0 = x.x - __bfloat162float(h0);
    float r1 = x.y - __bfloat162float(h1);
    float r2 = x.z - __bfloat162float(h2);
    float r3 = x.w - __bfloat162float(h3);
    __nv_bfloat162 ph0; ph0.x = h0; ph0.y = h1;
    __nv_bfloat162 ph1; ph1.x = h2; ph1.y = h3;
    uint2 hv = make_uint2(*reinterpret_cast<unsigned*>(&ph0),
                          *reinterpret_cast<unsigned*>(&ph1));
    uint2 lv = make_uint2(pack_bf2(r0, r1), pack_bf2(r2, r3));
    *reinterpret_cast<uint2*>(g_Vhi + i) = hv;
    *reinterpret_cast<uint2*>(g_Vlo + i) = lv;
}

// ---------------- kernel 2: dec projection + b_enc ----------------
__global__ void k_dec(const float* __restrict__ query,
                      const float* __restrict__ Wdec,
                      const float* __restrict__ b_enc) {
    __shared__ float q[DD];
    int b = blockIdx.x;
    int e = threadIdx.x;
    q[e] = query[b * DD + e];
    __syncthreads();
    float acc = b_enc[e];
    const float* wr = Wdec + e * DD;
#pragma unroll 8
    for (int d = 0; d < DD; ++d) acc += q[d] * wr[d];
    g_dec[b * DD + e] = acc;
}

// ---------------- kernel 3: location conv (att_prev -> [b][t][10]) ------
__global__ void k_conv(const float* __restrict__ att_prev,
                       const float* __restrict__ Wconv) {
    __shared__ float win[128 + 2 * FWD];   // 328
    __shared__ float wc[CCH * KW];         // 2010
    int t0 = blockIdx.x * 128;
    int b = blockIdx.y;
    int tid = threadIdx.x;                 // 128
    for (int i = tid; i < 128 + 2 * FWD; i += 128) {
        int gidx = t0 - FWD + i;
        win[i] = (gidx >= 0 && gidx < TT) ? att_prev[b * TT + gidx] : 0.f;
    }
    for (int i = tid; i < CCH * KW; i += 128) wc[i] = Wconv[i];
    __syncthreads();
    float acc[CCH];
#pragma unroll
    for (int c = 0; c < CCH; ++c) acc[c] = 0.f;
    for (int h = 0; h < KW; ++h) {
        float x = win[tid + h];
#pragma unroll
        for (int c = 0; c < CCH; ++c) acc[c] += x * wc[c * KW + h];
    }
    float* o = &g_conv[(size_t)(b * TT + t0 + tid) * CCH];
#pragma unroll
    for (int c = 0; c < CCH; ++c) o[c] = acc[c];
}

// ---------------- kernel 4: fused split-bf16 GEMM + epilogue -> logits --
// block tile: 128(t) x 128(e), KC=16, double-buffered cp.async,
// 256 threads (8 warps 4x2), 2 CTAs/SM
#define KC 16
#define NCHUNK (DD / KC)   // 32
struct SMain {
    unsigned Ahi[2][128][12];   // [stage][row][8 used + 4 pad] -> rows 48B
    unsigned Alo[2][128][12];
    unsigned Bhi[2][128][12];
    unsigned Blo[2][128][12];
};                              // 49152 bytes
struct SEpi {
    float conv[128][10];
    float watt[128][10];
    float dec[128];
    float wg[128];
    float red[128][2];
};
union SU { SMain m; SEpi e; };

__global__ void __launch_bounds__(256, 2)
k_gemm(const float* __restrict__ Watt,
       const float* __restrict__ wg) {
    __shared__ SU su;
    int tid = threadIdx.x;
    int b = blockIdx.z;
    int t0 = blockIdx.x * 128;
    int e0 = blockIdx.y * 128;
    int lane = tid & 31, warp = tid >> 5;
    int wm = warp & 3, wn = warp >> 2;         // 4 x 2 warps
    int g = lane >> 2, c = lane & 3;

    float acc[2][8][4];
#pragma unroll
    for (int mt = 0; mt < 2; ++mt)
#pragma unroll
        for (int nt = 0; nt < 8; ++nt)
#pragma unroll
            for (int q = 0; q < 4; ++q) acc[mt][nt][q] = 0.f;

    // shared byte addresses
    unsigned sAhi = (unsigned)__cvta_generic_to_shared(&su.m.Ahi[0][0][0]);
    unsigned sAlo = (unsigned)__cvta_generic_to_shared(&su.m.Alo[0][0][0]);
    unsigned sBhi = (unsigned)__cvta_generic_to_shared(&su.m.Bhi[0][0][0]);
    unsigned sBlo = (unsigned)__cvta_generic_to_shared(&su.m.Blo[0][0][0]);

    // cp.async mapping: thread -> (row, half16B)
    int crow = tid >> 1, chalf = tid & 1;
    const __nv_bfloat16* gAhi =
        g_Vhi + ((size_t)(b * TT + t0 + crow)) * DD + chalf * 8;
    const __nv_bfloat16* gAlo =
        g_Vlo + ((size_t)(b * TT + t0 + crow)) * DD + chalf * 8;
    const __nv_bfloat16* gBhi = g_Whi + (size_t)(e0 + crow) * DD + chalf * 8;
    const __nv_bfloat16* gBlo = g_Wlo + (size_t)(e0 + crow) * DD + chalf * 8;
    unsigned soff = (unsigned)((crow * 12 + chalf * 4) * 4);   // bytes

#define ISSUE_STAGE(s, k0)                                                   \
    do {                                                                     \
        unsigned sb = (unsigned)(s) * 128u * 12u * 4u + soff;                \
        CP_ASYNC16(sAhi + sb, gAhi + (k0));                                  \
        CP_ASYNC16(sAlo + sb, gAlo + (k0));                                  \
        CP_ASYNC16(sBhi + sb, gBhi + (k0));                                  \
        CP_ASYNC16(sBlo + sb, gBlo + (k0));                                  \
    } while (0)

    // ldmatrix per-lane address components
    int lr = ((lane >> 3) & 1) * 8 + (lane & 7);   // row within 16-row group
    int lc = ((lane >> 4) & 1) * 4;                // uint column (0 or 4)

    ISSUE_STAGE(0, 0); CP_COMMIT();
    ISSUE_STAGE(1, KC); CP_COMMIT();

    for (int it = 0; it < NCHUNK; ++it) {
        if (it < NCHUNK - 1) { CP_WAIT(1); } else { CP_WAIT(0); }
        __syncthreads();
        int s = it & 1;
        unsigned stb = (unsigned)s * 128u * 12u * 4u;

        unsigned ahi[2][4], alo[2][4];
#pragma unroll
        for (int mt = 0; mt < 2; ++mt) {
            unsigned ao = stb + (unsigned)(((wm * 32 + mt * 16 + lr) * 12 + lc) * 4);
            ldsm4(ahi[mt], sAhi + ao);
            ldsm4(alo[mt], sAlo + ao);
        }
#pragma unroll
        for (int ntp = 0; ntp < 4; ++ntp) {
            unsigned bo = stb + (unsigned)(((wn * 64 + ntp * 16 + lr) * 12 + lc) * 4);
            unsigned bh[4], bl[4];
            ldsm4(bh, sBhi + bo);
            ldsm4(bl, sBlo + bo);
#pragma unroll
            for (int sub = 0; sub < 2; ++sub) {
                int nt = ntp * 2 + sub;
                unsigned bh0 = bh[sub], bh1 = bh[2 + sub];
                unsigned bl0 = bl[sub], bl1 = bl[2 + sub];
#pragma unroll
                for (int mt = 0; mt < 2; ++mt) {
                    mma_bf16(acc[mt][nt], ahi[mt], bh0, bh1);
                    mma_bf16(acc[mt][nt], ahi[mt], bl0, bl1);
                    mma_bf16(acc[mt][nt], alo[mt], bh0, bh1);
                }
            }
        }
        __syncthreads();
        if (it < NCHUNK - 2) { ISSUE_STAGE(s, (it + 2) * KC); CP_COMMIT(); }
    }

    // ---- epilogue: + dec + conv@Watt, tanh, dot w_g, row-reduce ----
    for (int i = tid; i < 1280; i += 256) {
        int row = i / 10, cc = i - row * 10;
        su.e.conv[row][cc] = g_conv[(size_t)(b * TT + t0 + row) * CCH + cc];
        su.e.watt[row][cc] = Watt[(e0 + row) * CCH + cc];
    }
    if (tid < 128) {
        su.e.dec[tid] = g_dec[b * DD + e0 + tid];
        su.e.wg[tid] = wg[e0 + tid];
    }
    __syncthreads();

    float rowsum[2][2];
#pragma unroll
    for (int mt = 0; mt < 2; ++mt)
#pragma unroll
        for (int rr = 0; rr < 2; ++rr) {
            int rowl = wm * 32 + mt * 16 + rr * 8 + g;
            float sacc = 0.f;
#pragma unroll
            for (int nt = 0; nt < 8; ++nt)
#pragma unroll
                for (int q = 0; q < 2; ++q) {
                    int el = wn * 64 + nt * 8 + 2 * c + q;
                    float v = acc[mt][nt][rr * 2 + q] + su.e.dec[el];
#pragma unroll
                    for (int cc = 0; cc < CCH; ++cc)
                        v += su.e.conv[rowl][cc] * su.e.watt[el][cc];
                    sacc += su.e.wg[el] * tanhf(v);
                }
            rowsum[mt][rr] = sacc;
        }
#pragma unroll
    for (int mt = 0; mt < 2; ++mt)
#pragma unroll
        for (int rr = 0; rr < 2; ++rr) {
            float v = rowsum[mt][rr];
            v += __shfl_xor_sync(0xffffffffu, v, 1);
            v += __shfl_xor_sync(0xffffffffu, v, 2);
            rowsum[mt][rr] = v;
        }
    if (c == 0) {
#pragma unroll
        for (int mt = 0; mt < 2; ++mt)
#pragma unroll
            for (int rr = 0; rr < 2; ++rr)
                su.e.red[wm * 32 + mt * 16 + rr * 8 + g][wn] = rowsum[mt][rr];
    }
    __syncthreads();
    if (tid < 128) {
        float val = su.e.red[tid][0] + su.e.red[tid][1];
        g_epart[((size_t)blockIdx.y * BB + b) * TT + t0 + tid] = val;
    }
}

// ---------------- kernel 5: masked sharpened softmax ----------------
__global__ void k_softmax(const int* __restrict__ lens,
                          float* __restrict__ out_att) {
    int b = blockIdx.x;
    int tid = threadIdx.x;            // 256
    int len = lens[b];
    __shared__ float sred[256];
    float ev[16];
    float lmax = -INFINITY;
#pragma unroll
    for (int i = 0; i < 16; ++i) {
        int t = tid + i * 256;
        float e = g_epart[(0 * BB + b) * TT + t] +
                  g_epart[(1 * BB + b) * TT + t] +
                  g_epart[(2 * BB + b) * TT + t] +
                  g_epart[(3 * BB + b) * TT + t];
        e *= 2.0f;                    // sharpening
        ev[i] = (t < len) ? e : -INFINITY;
        lmax = fmaxf(lmax, ev[i]);
    }
    sred[tid] = lmax;
    __syncthreads();
    for (int s = 128; s > 0; s >>= 1) {
        if (tid < s) sred[tid] = fmaxf(sred[tid], sred[tid + s]);
        __syncthreads();
    }
    float m = sred[0];
    __syncthreads();
    float lsum = 0.f;
#pragma unroll
    for (int i = 0; i < 16; ++i) {
        float p = expf(ev[i] - m);    // exp(-inf)=0 for masked
        ev[i] = p;
        lsum += p;
    }
    sred[tid] = lsum;
    __syncthreads();
    for (int s = 128; s > 0; s >>= 1) {
        if (tid < s) sred[tid] += sred[tid + s];
        __syncthreads();
    }
    float inv = 1.f / sred[0];
#pragma unroll
    for (int i = 0; i < 16; ++i)
        out_att[b * TT + tid + i * 256] = ev[i] * inv;
}

// ---------------- kernel 6/7: context = value^T @ weights ----------------
__global__ void k_ctx_part(const float* __restrict__ value,
                           const float* __restrict__ att) {
    int dch = blockIdx.x, tch = blockIdx.y, b = blockIdx.z;
    int dl = threadIdx.x & 127;
    int tl = threadIdx.x >> 7;        // 0/1
    int d = dch * 128 + dl;
    const float* vb = value + (size_t)b * TT * DD;
    const float* ab = att + b * TT;
    float acc = 0.f;
    int tbase = tch * 512;
    for (int t = tbase + tl; t < tbase + 512; t += 2)
        acc += vb[(size_t)t * DD + d] * ab[t];
    __shared__ float s[256];
    s[threadIdx.x] = acc;
    __syncthreads();
    if (tl == 0)
        g_ctxpart[((size_t)tch * BB + b) * DD + d] = s[dl] + s[dl + 128];
}

__global__ void k_ctx_final(float* __restrict__ out) {
    int idx = blockIdx.x * 256 + threadIdx.x;    // < BB*DD
    float v = 0.f;
#pragma unroll
    for (int p = 0; p < 8; ++p) v += g_ctxpart[p * BB * DD + idx];
    out[idx] = v;
}

// ---------------- launch ----------------
extern "C" void kernel_launch(void* const* d_in, const int* in_sizes, int n_in,
                              void* d_out, int out_size) {
    const float* value    = (const float*)d_in[0];
    const float* query    = (const float*)d_in[1];
    const int*   lens     = (const int*)d_in[2];
    const float* att_prev = (const float*)d_in[3];
    const float* W_enc    = (const float*)d_in[4];
    const float* b_enc    = (const float*)d_in[5];
    const float* W_dec    = (const float*)d_in[6];
    const float* W_att    = (const float*)d_in[7];
    const float* W_conv   = (const float*)d_in[8];
    const float* w_g      = (const float*)d_in[9];
    // d_in[10] = b_g: uniform logit shift, cancels in softmax.

    float* out = (float*)d_out;
    float* out_att = out + BB * DD;

    k_split<<<512, 512>>>(W_enc);
    k_vsplit<<<(BB * TT * DD) / (4 * 256), 256>>>(value);
    k_dec<<<BB, DD>>>(query, W_dec, b_enc);
    k_conv<<<dim3(TT / 128, BB), 128>>>(att_prev, W_conv);
    k_gemm<<<dim3(TT / 128, NBLK, BB), 256>>>(W_att, w_g);
    k_softmax<<<BB, 256>>>(lens, out_att);
    k_ctx_part<<<dim3(4, 8, BB), 256>>>(value, out_att);
    k_ctx_final<<<BB * DD / 256, 256>>>(out);
}